// round 8
// baseline (speedup 1.0000x reference)
#include <cuda_runtime.h>
#include <cuda_bf16.h>
#include <math.h>
#include <stdint.h>

#define Bx 512
#define Tt 256
#define Ii 128
#define Hh 512
#define G3 1536

// ---------------- scratch (device globals; no allocation allowed) ----------------
__device__ float g_xg[(size_t)Tt * (size_t)Bx * (size_t)G3]; // [T][B][3H] fp32
__device__ float g_h[2][Bx * Hh];                            // fp32 hidden, ping-pong
__device__ __nv_bfloat16 g_hhi[2][Bx * Hh];                  // h split-bf16 hi (perm-k)
__device__ __nv_bfloat16 g_hlo[2][Bx * Hh];                  // h split-bf16 lo (perm-k)
__device__ __nv_bfloat16 g_Whi[(size_t)G3 * Hh];             // W_hh bf16 hi (perm-k)
__device__ __nv_bfloat16 g_Wlo[(size_t)G3 * Hh];             // W_hh bf16 lo (perm-k)

// permutation within each 16-k block so mma fragment (k, k+1, k+8, k+9) is one LDS.64
__device__ __forceinline__ int kperm(int k) {
    return ((k & 7) >> 1) * 4 + (k & 1) + (((k >> 3) & 1) << 1);
}

// ---------------- init: zero h0 (fp32 + bf16 hi/lo), every launch ---------------
__global__ void init_kernel() {
    int i = blockIdx.x * 256 + threadIdx.x;
    if (i < Bx * Hh) {
        g_h[0][i] = 0.0f;
        g_hhi[0][i] = __float2bfloat16(0.0f);
        g_hlo[0][i] = __float2bfloat16(0.0f);
    }
}

// ---------------- W_hh -> split bf16, permuted-k layout (once per launch) --------
__global__ void wconv_kernel(const float* __restrict__ Whh) {
    int idx = blockIdx.x * 256 + threadIdx.x;
    if (idx >= G3 * Hh) return;
    int row = idx >> 9, k = idx & 511;
    float w = Whh[idx];
    __nv_bfloat16 hi = __float2bfloat16(w);
    float lo = w - __bfloat162float(hi);
    int kk = (k & ~15) + kperm(k & 15);
    g_Whi[(size_t)row * Hh + kk] = hi;
    g_Wlo[(size_t)row * Hh + kk] = __float2bfloat16(lo);
}

// ---------------- kernel 1: xg[t][b][g] = x[b,t,:] @ W_ih[g,:] + bias ------------
// bias = b_ih + b_hh for r/z gates; b_ih only for n gate (b_hh_n sits inside r*hn).
__global__ __launch_bounds__(256) void xg_kernel(
    const float* __restrict__ x, const float* __restrict__ Wih,
    const float* __restrict__ bih, const float* __restrict__ bhh)
{
    __shared__ float As[64][68];
    __shared__ float Bs[64][68];
    const int bt0 = blockIdx.x * 64;
    const int n0  = blockIdx.y * 64;
    const int tid = threadIdx.x;
    const int tx = tid & 15, ty = tid >> 4;

    float acc[4][4];
#pragma unroll
    for (int i = 0; i < 4; ++i)
#pragma unroll
        for (int j = 0; j < 4; ++j) acc[i][j] = 0.0f;

    for (int kc = 0; kc < 2; ++kc) {
        const int kb = kc * 64;
#pragma unroll
        for (int i = 0; i < 4; ++i) {
            int q = tid + 256 * i;
            int r = q >> 4, c4 = q & 15;
            float4 v = *(const float4*)(x + (size_t)(bt0 + r) * Ii + kb + c4 * 4);
            As[c4 * 4 + 0][r] = v.x; As[c4 * 4 + 1][r] = v.y;
            As[c4 * 4 + 2][r] = v.z; As[c4 * 4 + 3][r] = v.w;
        }
#pragma unroll
        for (int i = 0; i < 4; ++i) {
            int q = tid + 256 * i;
            int r = q >> 4, c4 = q & 15;
            float4 v = *(const float4*)(Wih + (size_t)(n0 + r) * Ii + kb + c4 * 4);
            Bs[c4 * 4 + 0][r] = v.x; Bs[c4 * 4 + 1][r] = v.y;
            Bs[c4 * 4 + 2][r] = v.z; Bs[c4 * 4 + 3][r] = v.w;
        }
        __syncthreads();
#pragma unroll 16
        for (int k = 0; k < 64; ++k) {
            float4 a4 = *(const float4*)&As[k][ty * 4];
            float4 b4 = *(const float4*)&Bs[k][tx * 4];
            float av[4] = {a4.x, a4.y, a4.z, a4.w};
            float bv[4] = {b4.x, b4.y, b4.z, b4.w};
#pragma unroll
            for (int i = 0; i < 4; ++i)
#pragma unroll
                for (int j = 0; j < 4; ++j) acc[i][j] += av[i] * bv[j];
        }
        __syncthreads();
    }

#pragma unroll
    for (int i = 0; i < 4; ++i) {
        int bt = bt0 + ty * 4 + i;
        int b = bt / Tt, t = bt % Tt;       // x rows are [B][T]
        float* dst = g_xg + ((size_t)t * Bx + b) * G3 + n0 + tx * 4;
#pragma unroll
        for (int j = 0; j < 4; ++j) {
            int g = n0 + tx * 4 + j;
            float bias = bih[g] + (g < 2 * Hh ? bhh[g] : 0.0f);
            dst[j] = acc[i][j] + bias;
        }
    }
}

// ---------------- bf16 mma.sync helper ------------------------------------------
__device__ __forceinline__ void mma_bf16(float* c,
    uint32_t a0, uint32_t a1, uint32_t a2, uint32_t a3,
    uint32_t b0, uint32_t b1)
{
    asm volatile(
        "mma.sync.aligned.m16n8k16.row.col.f32.bf16.bf16.f32 "
        "{%0,%1,%2,%3},{%4,%5,%6,%7},{%8,%9},{%0,%1,%2,%3};"
        : "+f"(c[0]), "+f"(c[1]), "+f"(c[2]), "+f"(c[3])
        : "r"(a0), "r"(a1), "r"(a2), "r"(a3), "r"(b0), "r"(b1));
}

// smem row strides (bf16 units): 80 -> 160B rows, conflict-free LDS.64 fragments
#define AST 80
#define BST 80
// per-stage partition (bf16 units)
#define OFF_AHI 0
#define OFF_ALO (64 * AST)
#define OFF_BHI (2 * 64 * AST)
#define OFF_BLO (2 * 64 * AST + 96 * BST)
#define STAGE_ELEMS (2 * 64 * AST + 2 * 96 * BST)       // 25600 bf16 = 51200 B
#define SMEM_BYTES (2 * STAGE_ELEMS * 2)                // 2 stages = 102400 B

// ---------------- kernel 2: one GRU timestep (tensor-core, split-bf16) -----------
// 512 threads / 16 warps per block: each warp owns a 16-row x 8-col tile across
// all 3 gates (half the round-6 per-warp work -> 2x warp parallelism per SM).
// Double-buffered LDG->reg->STS pipeline, ONE sync per chunk:
//   iter ch: STS(chunk ch+1 from regs) | LDG(chunk ch+2 into regs) | MMA(chunk ch)
__global__ __launch_bounds__(512) void gru_step_kernel(
    int t, const float* __restrict__ bhh)
{
    extern __shared__ __nv_bfloat16 sm[];

    const int tid  = threadIdx.x;
    const int lane = tid & 31;
    const int w    = tid >> 5;          // 16 warps
    const int mt   = w >> 2;            // 4 m-tiles of 16 batch rows
    const int jp   = w & 3;             // 4 j-groups of 8 cols
    const int qrow = lane >> 2;         // 0..7
    const int qcol = lane & 3;          // 0..3

    const int btile = blockIdx.x >> 4, jtile = blockIdx.x & 15;
    const int b0 = btile * 64, j0 = jtile * 32;

    const __nv_bfloat16* hhi_in = g_hhi[t & 1];
    const __nv_bfloat16* hlo_in = g_hlo[t & 1];

    // staging decomposition: 512 threads, each does A row sr (hi+lo) and
    // B rows sr and sr+64 (the latter only for sr<32)
    const int sr  = tid >> 3;           // 0..63
    const int pos = tid & 7;            // 16B slot within 128B row

    uint4 ra_hi, ra_lo, rb_hi[2], rb_lo[2];   // in-flight chunk registers

    auto load_regs = [&](int ch) {
        const int kb = ch * 64;
        {
            size_t goff = (size_t)(b0 + sr) * Hh + kb + pos * 8;
            ra_hi = *(const uint4*)(hhi_in + goff);
            ra_lo = *(const uint4*)(hlo_in + goff);
        }
        {
            int grow = ((sr >> 5) << 9) + j0 + (sr & 31);
            size_t goff = (size_t)grow * Hh + kb + pos * 8;
            rb_hi[0] = *(const uint4*)(g_Whi + goff);
            rb_lo[0] = *(const uint4*)(g_Wlo + goff);
        }
        if (sr < 32) {
            int p = sr + 64;            // rows 64..95 (n gate)
            int grow = (2 << 9) + j0 + (p & 31);
            size_t goff = (size_t)grow * Hh + kb + pos * 8;
            rb_hi[1] = *(const uint4*)(g_Whi + goff);
            rb_lo[1] = *(const uint4*)(g_Wlo + goff);
        }
    };
    auto sts_regs = [&](int s) {
        __nv_bfloat16* st = sm + s * STAGE_ELEMS;
        *(uint4*)&st[OFF_AHI + sr * AST + pos * 8] = ra_hi;
        *(uint4*)&st[OFF_ALO + sr * AST + pos * 8] = ra_lo;
        *(uint4*)&st[OFF_BHI + sr * BST + pos * 8] = rb_hi[0];
        *(uint4*)&st[OFF_BLO + sr * BST + pos * 8] = rb_lo[0];
        if (sr < 32) {
            int p = sr + 64;
            *(uint4*)&st[OFF_BHI + p * BST + pos * 8] = rb_hi[1];
            *(uint4*)&st[OFF_BLO + p * BST + pos * 8] = rb_lo[1];
        }
    };

    // prologue: chunk0 -> stage0; chunk1 in registers
    load_regs(0);
    sts_regs(0);
    load_regs(1);

    // -------- epilogue operand prefetch (overlaps the whole GEMM) --------
    const float* xg_t = g_xg + (size_t)t * Bx * G3;
    const float* hf_in = g_h[t & 1];
    float pre_xr[4], pre_xz[4], pre_xn[4], pre_h[4], pre_bn[4];
#pragma unroll
    for (int e = 0; e < 4; ++e) {
        int row = b0 + mt * 16 + qrow + ((e >> 1) ? 8 : 0);
        int j   = j0 + jp * 8 + qcol * 2 + (e & 1);
        const float* xp = xg_t + (size_t)row * G3 + j;
        pre_xr[e] = xp[0];
        pre_xz[e] = xp[Hh];
        pre_xn[e] = xp[2 * Hh];
        pre_h[e]  = hf_in[row * Hh + j];
        pre_bn[e] = bhh[2 * Hh + j];
    }
    __syncthreads();   // stage0 published

    float acc[3][4];                    // [gate][c-regs]
#pragma unroll
    for (int g = 0; g < 3; ++g)
#pragma unroll
        for (int e = 0; e < 4; ++e) acc[g][e] = 0.0f;

    const int ar0 = mt * 16 + qrow;
    const int ar8 = ar0 + 8;

#pragma unroll 1
    for (int ch = 0; ch < 8; ++ch) {
        // STS chunk ch+1 (regs) into the buffer consumed at ch-1; safe: one
        // barrier separates its last read (mma ch-1) from this write.
        if (ch < 7) sts_regs((ch + 1) & 1);
        if (ch < 6) load_regs(ch + 2);      // LDG issue; consumed next iter

        const __nv_bfloat16* st = sm + (ch & 1) * STAGE_ELEMS;
        const __nv_bfloat16* As_hi = st + OFF_AHI;
        const __nv_bfloat16* As_lo = st + OFF_ALO;
        const __nv_bfloat16* Bs_hi = st + OFF_BHI;
        const __nv_bfloat16* Bs_lo = st + OFF_BLO;

#pragma unroll
        for (int kt = 0; kt < 4; ++kt) {
            const int aoff = kt * 16 + qcol * 4;
            uint2 ah0 = *(const uint2*)&As_hi[ar0 * AST + aoff];
            uint2 ah8 = *(const uint2*)&As_hi[ar8 * AST + aoff];
            uint2 al0 = *(const uint2*)&As_lo[ar0 * AST + aoff];
            uint2 al8 = *(const uint2*)&As_lo[ar8 * AST + aoff];
#pragma unroll
            for (int g = 0; g < 3; ++g) {
                int brow = g * 32 + jp * 8 + qrow;
                uint2 bh = *(const uint2*)&Bs_hi[brow * BST + aoff];
                uint2 bl = *(const uint2*)&Bs_lo[brow * BST + aoff];
                float* c = acc[g];
                mma_bf16(c, ah0.x, ah8.x, ah0.y, ah8.y, bh.x, bh.y);
                mma_bf16(c, ah0.x, ah8.x, ah0.y, ah8.y, bl.x, bl.y);
                mma_bf16(c, al0.x, al8.x, al0.y, al8.y, bh.x, bh.y);
            }
        }
        if (ch < 7) __syncthreads();    // publish stage (ch+1)&1, fence reads
    }

    // -------- epilogue: gates fused in registers --------
    float* hf_out = g_h[(t + 1) & 1];
    __nv_bfloat16* hhi_out = g_hhi[(t + 1) & 1];
    __nv_bfloat16* hlo_out = g_hlo[(t + 1) & 1];

#pragma unroll
    for (int e = 0; e < 4; ++e) {
        int row = b0 + mt * 16 + qrow + ((e >> 1) ? 8 : 0);
        int j   = j0 + jp * 8 + qcol * 2 + (e & 1);
        float hr = acc[0][e];
        float hz = acc[1][e];
        float hn = acc[2][e] + pre_bn[e];   // b_hh_n inside r*hn
        float r = 1.0f / (1.0f + expf(-(pre_xr[e] + hr)));
        float z = 1.0f / (1.0f + expf(-(pre_xz[e] + hz)));
        float n = tanhf(pre_xn[e] + r * hn);
        float hnew = (1.0f - z) * n + z * pre_h[e];
        hf_out[row * Hh + j] = hnew;
        __nv_bfloat16 hi = __float2bfloat16(hnew);
        float lo = hnew - __bfloat162float(hi);
        int jj = (j & ~15) + kperm(j & 15);
        hhi_out[row * Hh + jj] = hi;
        hlo_out[row * Hh + jj] = __float2bfloat16(lo);
    }
}

// ---------------- kernel 3: out[b] = h_T[b,:] @ W_lin + b_lin -------------------
__global__ void out_kernel(const float* __restrict__ Wlin,
                           const float* __restrict__ blin,
                           float* __restrict__ out)
{
    int w = (blockIdx.x * blockDim.x + threadIdx.x) >> 5;
    int lane = threadIdx.x & 31;
    if (w >= Bx) return;
    const float* h = g_h[0] + (size_t)w * Hh;   // T=256 even -> final in buf 0
    float s = 0.0f;
#pragma unroll
    for (int i = 0; i < Hh / 32; ++i) s += h[lane + 32 * i] * Wlin[lane + 32 * i];
#pragma unroll
    for (int o = 16; o; o >>= 1) s += __shfl_xor_sync(0xffffffffu, s, o);
    if (lane == 0) out[w] = s + blin[0];
}

// ---------------- launch ---------------------------------------------------------
extern "C" void kernel_launch(void* const* d_in, const int* in_sizes, int n_in,
                              void* d_out, int out_size)
{
    const float* x    = (const float*)d_in[0];
    const float* Wih  = (const float*)d_in[1];
    const float* Whh  = (const float*)d_in[2];
    const float* bih  = (const float*)d_in[3];
    const float* bhh  = (const float*)d_in[4];
    const float* Wlin = (const float*)d_in[5];
    const float* blin = (const float*)d_in[6];
    float* out = (float*)d_out;

    cudaFuncSetAttribute(gru_step_kernel,
                         cudaFuncAttributeMaxDynamicSharedMemorySize, SMEM_BYTES);

    init_kernel<<<(Bx * Hh + 255) / 256, 256>>>();
    wconv_kernel<<<(G3 * Hh + 255) / 256, 256>>>(Whh);
    dim3 gx((Bx * Tt) / 64, G3 / 64);
    xg_kernel<<<gx, 256>>>(x, Wih, bih, bhh);
    for (int t = 0; t < Tt; ++t)
        gru_step_kernel<<<128, 512, SMEM_BYTES>>>(t, bhh);
    out_kernel<<<(Bx * 32) / 256, 256>>>(Wlin, blin, out);
}

// round 9
// speedup vs baseline: 1.0653x; 1.0653x over previous
#include <cuda_runtime.h>
#include <cuda_bf16.h>
#include <math.h>
#include <stdint.h>

#define Bx 512
#define Tt 256
#define Ii 128
#define Hh 512
#define G3 1536
#define NBLK 128   // 8 b-tiles x 16 j-tiles; <=148 SMs, 1 CTA/SM -> co-resident

// ---------------- scratch (device globals; no allocation allowed) ----------------
__device__ float g_xg[(size_t)Tt * (size_t)Bx * (size_t)G3]; // [T][B][3H] fp32
__device__ float g_h[2][Bx * Hh];                            // fp32 hidden, ping-pong
__device__ __nv_bfloat16 g_hhi[2][Bx * Hh];                  // h split-bf16 hi (perm-k)
__device__ __nv_bfloat16 g_hlo[2][Bx * Hh];                  // h split-bf16 lo (perm-k)
__device__ __nv_bfloat16 g_Whi[(size_t)G3 * Hh];             // W_hh bf16 hi (perm-k)
__device__ __nv_bfloat16 g_Wlo[(size_t)G3 * Hh];             // W_hh bf16 lo (perm-k)
__device__ unsigned g_bar_cnt;
__device__ volatile unsigned g_bar_gen;

// permutation within each 16-k block so mma fragment (k, k+1, k+8, k+9) is one LDS.64
__device__ __forceinline__ int kperm(int k) {
    return ((k & 7) >> 1) * 4 + (k & 1) + (((k >> 3) & 1) << 1);
}

// ---------------- init: zero h0 + barrier state (every launch) -------------------
__global__ void init_kernel() {
    int i = blockIdx.x * 256 + threadIdx.x;
    if (i < Bx * Hh) {
        g_h[0][i] = 0.0f;
        g_hhi[0][i] = __float2bfloat16(0.0f);
        g_hlo[0][i] = __float2bfloat16(0.0f);
    }
    if (i == 0) { g_bar_cnt = 0u; g_bar_gen = 0u; }
}

// ---------------- W_hh -> split bf16, permuted-k layout (once per launch) --------
__global__ void wconv_kernel(const float* __restrict__ Whh) {
    int idx = blockIdx.x * 256 + threadIdx.x;
    if (idx >= G3 * Hh) return;
    int row = idx >> 9, k = idx & 511;
    float w = Whh[idx];
    __nv_bfloat16 hi = __float2bfloat16(w);
    float lo = w - __bfloat162float(hi);
    int kk = (k & ~15) + kperm(k & 15);
    g_Whi[(size_t)row * Hh + kk] = hi;
    g_Wlo[(size_t)row * Hh + kk] = __float2bfloat16(lo);
}

// ---------------- kernel 1: xg[t][b][g] = x[b,t,:] @ W_ih[g,:] + bias ------------
// bias = b_ih + b_hh for r/z gates; b_ih only for n gate (b_hh_n sits inside r*hn).
__global__ __launch_bounds__(256) void xg_kernel(
    const float* __restrict__ x, const float* __restrict__ Wih,
    const float* __restrict__ bih, const float* __restrict__ bhh)
{
    __shared__ float As[64][68];
    __shared__ float Bs[64][68];
    const int bt0 = blockIdx.x * 64;
    const int n0  = blockIdx.y * 64;
    const int tid = threadIdx.x;
    const int tx = tid & 15, ty = tid >> 4;

    float acc[4][4];
#pragma unroll
    for (int i = 0; i < 4; ++i)
#pragma unroll
        for (int j = 0; j < 4; ++j) acc[i][j] = 0.0f;

    for (int kc = 0; kc < 2; ++kc) {
        const int kb = kc * 64;
#pragma unroll
        for (int i = 0; i < 4; ++i) {
            int q = tid + 256 * i;
            int r = q >> 4, c4 = q & 15;
            float4 v = *(const float4*)(x + (size_t)(bt0 + r) * Ii + kb + c4 * 4);
            As[c4 * 4 + 0][r] = v.x; As[c4 * 4 + 1][r] = v.y;
            As[c4 * 4 + 2][r] = v.z; As[c4 * 4 + 3][r] = v.w;
        }
#pragma unroll
        for (int i = 0; i < 4; ++i) {
            int q = tid + 256 * i;
            int r = q >> 4, c4 = q & 15;
            float4 v = *(const float4*)(Wih + (size_t)(n0 + r) * Ii + kb + c4 * 4);
            Bs[c4 * 4 + 0][r] = v.x; Bs[c4 * 4 + 1][r] = v.y;
            Bs[c4 * 4 + 2][r] = v.z; Bs[c4 * 4 + 3][r] = v.w;
        }
        __syncthreads();
#pragma unroll 16
        for (int k = 0; k < 64; ++k) {
            float4 a4 = *(const float4*)&As[k][ty * 4];
            float4 b4 = *(const float4*)&Bs[k][tx * 4];
            float av[4] = {a4.x, a4.y, a4.z, a4.w};
            float bv[4] = {b4.x, b4.y, b4.z, b4.w};
#pragma unroll
            for (int i = 0; i < 4; ++i)
#pragma unroll
                for (int j = 0; j < 4; ++j) acc[i][j] += av[i] * bv[j];
        }
        __syncthreads();
    }

#pragma unroll
    for (int i = 0; i < 4; ++i) {
        int bt = bt0 + ty * 4 + i;
        int b = bt / Tt, t = bt % Tt;       // x rows are [B][T]
        float* dst = g_xg + ((size_t)t * Bx + b) * G3 + n0 + tx * 4;
#pragma unroll
        for (int j = 0; j < 4; ++j) {
            int g = n0 + tx * 4 + j;
            float bias = bih[g] + (g < 2 * Hh ? bhh[g] : 0.0f);
            dst[j] = acc[i][j] + bias;
        }
    }
}

// ---------------- bf16 mma.sync helper ------------------------------------------
__device__ __forceinline__ void mma_bf16(float* c,
    uint32_t a0, uint32_t a1, uint32_t a2, uint32_t a3,
    uint32_t b0, uint32_t b1)
{
    asm volatile(
        "mma.sync.aligned.m16n8k16.row.col.f32.bf16.bf16.f32 "
        "{%0,%1,%2,%3},{%4,%5,%6,%7},{%8,%9},{%0,%1,%2,%3};"
        : "+f"(c[0]), "+f"(c[1]), "+f"(c[2]), "+f"(c[3])
        : "r"(a0), "r"(a1), "r"(a2), "r"(a3), "r"(b0), "r"(b1));
}

// smem row strides (bf16 units): 80 -> 160B rows, conflict-free LDS.64 fragments
#define AST 80
#define BST 80
// per-stage partition (bf16 units)
#define OFF_AHI 0
#define OFF_ALO (64 * AST)
#define OFF_BHI (2 * 64 * AST)
#define OFF_BLO (2 * 64 * AST + 96 * BST)
#define STAGE_ELEMS (2 * 64 * AST + 2 * 96 * BST)       // 25600 bf16 = 51200 B
#define SMEM_BYTES (2 * STAGE_ELEMS * 2)                // 2 stages = 102400 B

// ---------------- grid barrier (128 co-resident CTAs) ----------------------------
__device__ __forceinline__ void gridbar() {
    __syncthreads();
    if (threadIdx.x == 0) {
        __threadfence();                       // publish this block's stores
        unsigned gen = g_bar_gen;
        if (atomicAdd(&g_bar_cnt, 1u) == NBLK - 1u) {
            g_bar_cnt = 0u;
            __threadfence();
            g_bar_gen = gen + 1u;
        } else {
            while (g_bar_gen == gen) __nanosleep(64);
        }
        __threadfence();                       // acquire side
    }
    __syncthreads();
}

// ---------------- kernel 2: persistent GRU (tensor-core, split-bf16) -------------
// All 256 timesteps in one launch; grid barrier between steps. Round-6 step
// pipeline (256 thr, 16x16 warp tiles, double-buffered LDG->reg->STS, one sync
// per chunk). Cross-block h traffic via __ldcg (L1 incoherent within launch);
// W stays on the L1-cached path and gets hot across steps.
__global__ __launch_bounds__(256, 1) void gru_persist_kernel(
    const float* __restrict__ bhh)
{
    extern __shared__ __nv_bfloat16 sm[];

    const int tid  = threadIdx.x;
    const int lane = tid & 31;
    const int w    = tid >> 5;          // 8 warps
    const int mt   = w >> 1;            // 4 m-tiles of 16 batch rows
    const int jp   = w & 1;             // 2 j-halves of 16 cols
    const int qrow = lane >> 2;         // 0..7
    const int qcol = lane & 3;          // 0..3

    const int btile = blockIdx.x >> 4, jtile = blockIdx.x & 15;
    const int b0 = btile * 64, j0 = jtile * 32;

    const int sr  = tid >> 3;           // 0..31 (row group; +32/+64 offsets)
    const int pos = tid & 7;            // 16B slot within 128B row

    const int ar0 = mt * 16 + qrow;
    const int ar8 = ar0 + 8;

    // per-thread epilogue coordinates (constant across steps)
    int erow[2][4], ej[2][4];
    float pre_bn[2][4];
#pragma unroll
    for (int nt = 0; nt < 2; ++nt)
#pragma unroll
        for (int e = 0; e < 4; ++e) {
            erow[nt][e] = b0 + mt * 16 + qrow + ((e >> 1) ? 8 : 0);
            ej[nt][e]   = j0 + jp * 16 + nt * 8 + qcol * 2 + (e & 1);
            pre_bn[nt][e] = bhh[2 * Hh + ej[nt][e]];
        }

    uint4 ra_hi[2], ra_lo[2], rb_hi[3], rb_lo[3];   // in-flight chunk registers

    // prefetch xg for t=0 (write-once data; safe pre-barrier anytime)
    float pxr[2][4], pxz[2][4], pxn[2][4];
#pragma unroll
    for (int nt = 0; nt < 2; ++nt)
#pragma unroll
        for (int e = 0; e < 4; ++e) {
            const float* xp = g_xg + (size_t)erow[nt][e] * G3 + ej[nt][e];
            pxr[nt][e] = xp[0];
            pxz[nt][e] = xp[Hh];
            pxn[nt][e] = xp[2 * Hh];
        }

#pragma unroll 1
    for (int t = 0; t < Tt; ++t) {
        const __nv_bfloat16* hhi_in = g_hhi[t & 1];
        const __nv_bfloat16* hlo_in = g_hlo[t & 1];
        const float* hf_in = g_h[t & 1];
        float* hf_out = g_h[(t + 1) & 1];
        __nv_bfloat16* hhi_out = g_hhi[(t + 1) & 1];
        __nv_bfloat16* hlo_out = g_hlo[(t + 1) & 1];

        auto load_regs = [&](int ch) {
            const int kb = ch * 64;
#pragma unroll
            for (int i = 0; i < 2; ++i) {
                int r = sr + 32 * i;
                size_t goff = (size_t)(b0 + r) * Hh + kb + pos * 8;
                ra_hi[i] = __ldcg((const uint4*)(hhi_in + goff));
                ra_lo[i] = __ldcg((const uint4*)(hlo_in + goff));
            }
#pragma unroll
            for (int i = 0; i < 3; ++i) {
                int p = sr + 32 * i;
                int grow = ((p >> 5) << 9) + j0 + (p & 31);
                size_t goff = (size_t)grow * Hh + kb + pos * 8;
                rb_hi[i] = *(const uint4*)(g_Whi + goff);   // L1-cached, reused
                rb_lo[i] = *(const uint4*)(g_Wlo + goff);
            }
        };
        auto sts_regs = [&](int s) {
            __nv_bfloat16* st = sm + s * STAGE_ELEMS;
#pragma unroll
            for (int i = 0; i < 2; ++i) {
                int r = sr + 32 * i;
                *(uint4*)&st[OFF_AHI + r * AST + pos * 8] = ra_hi[i];
                *(uint4*)&st[OFF_ALO + r * AST + pos * 8] = ra_lo[i];
            }
#pragma unroll
            for (int i = 0; i < 3; ++i) {
                int p = sr + 32 * i;
                *(uint4*)&st[OFF_BHI + p * BST + pos * 8] = rb_hi[i];
                *(uint4*)&st[OFF_BLO + p * BST + pos * 8] = rb_lo[i];
            }
        };

        // h_prev for this step (written by other blocks last step -> post-barrier)
        float pre_h[2][4];
#pragma unroll
        for (int nt = 0; nt < 2; ++nt)
#pragma unroll
            for (int e = 0; e < 4; ++e)
                pre_h[nt][e] = __ldcg(hf_in + (size_t)erow[nt][e] * Hh + ej[nt][e]);

        load_regs(0);
        sts_regs(0);
        load_regs(1);
        __syncthreads();    // stage0 published

        float acc[3][2][4];
#pragma unroll
        for (int g = 0; g < 3; ++g)
#pragma unroll
            for (int nt = 0; nt < 2; ++nt)
#pragma unroll
                for (int e = 0; e < 4; ++e) acc[g][nt][e] = 0.0f;

#pragma unroll 1
        for (int ch = 0; ch < 8; ++ch) {
            if (ch < 7) sts_regs((ch + 1) & 1);
            if (ch < 6) load_regs(ch + 2);

            const __nv_bfloat16* st = sm + (ch & 1) * STAGE_ELEMS;
            const __nv_bfloat16* As_hi = st + OFF_AHI;
            const __nv_bfloat16* As_lo = st + OFF_ALO;
            const __nv_bfloat16* Bs_hi = st + OFF_BHI;
            const __nv_bfloat16* Bs_lo = st + OFF_BLO;

#pragma unroll
            for (int kt = 0; kt < 4; ++kt) {
                const int aoff = kt * 16 + qcol * 4;
                uint2 ah0 = *(const uint2*)&As_hi[ar0 * AST + aoff];
                uint2 ah8 = *(const uint2*)&As_hi[ar8 * AST + aoff];
                uint2 al0 = *(const uint2*)&As_lo[ar0 * AST + aoff];
                uint2 al8 = *(const uint2*)&As_lo[ar8 * AST + aoff];
#pragma unroll
                for (int g = 0; g < 3; ++g)
#pragma unroll
                    for (int nt = 0; nt < 2; ++nt) {
                        int brow = g * 32 + jp * 16 + nt * 8 + qrow;
                        uint2 bh = *(const uint2*)&Bs_hi[brow * BST + aoff];
                        uint2 bl = *(const uint2*)&Bs_lo[brow * BST + aoff];
                        float* c = acc[g][nt];
                        mma_bf16(c, ah0.x, ah8.x, ah0.y, ah8.y, bh.x, bh.y);
                        mma_bf16(c, ah0.x, ah8.x, ah0.y, ah8.y, bl.x, bl.y);
                        mma_bf16(c, al0.x, al8.x, al0.y, al8.y, bh.x, bh.y);
                    }
            }
            if (ch < 7) __syncthreads();
        }

        // prefetch next step's xg (write-once; overlaps epilogue + barrier wait)
        float nxr[2][4], nxz[2][4], nxn[2][4];
        if (t + 1 < Tt) {
            const float* xg_n = g_xg + (size_t)(t + 1) * Bx * G3;
#pragma unroll
            for (int nt = 0; nt < 2; ++nt)
#pragma unroll
                for (int e = 0; e < 4; ++e) {
                    const float* xp = xg_n + (size_t)erow[nt][e] * G3 + ej[nt][e];
                    nxr[nt][e] = xp[0];
                    nxz[nt][e] = xp[Hh];
                    nxn[nt][e] = xp[2 * Hh];
                }
        }

        // -------- epilogue: gates fused in registers --------
#pragma unroll
        for (int nt = 0; nt < 2; ++nt)
#pragma unroll
            for (int e = 0; e < 4; ++e) {
                int row = erow[nt][e], j = ej[nt][e];
                float hr = acc[0][nt][e];
                float hz = acc[1][nt][e];
                float hn = acc[2][nt][e] + pre_bn[nt][e];   // b_hh_n inside r*hn
                float r = 1.0f / (1.0f + expf(-(pxr[nt][e] + hr)));
                float z = 1.0f / (1.0f + expf(-(pxz[nt][e] + hz)));
                float n = tanhf(pxn[nt][e] + r * hn);
                float hnew = (1.0f - z) * n + z * pre_h[nt][e];
                hf_out[row * Hh + j] = hnew;
                __nv_bfloat16 hi = __float2bfloat16(hnew);
                float lo = hnew - __bfloat162float(hi);
                int jj = (j & ~15) + kperm(j & 15);
                hhi_out[row * Hh + jj] = hi;
                hlo_out[row * Hh + jj] = __float2bfloat16(lo);
            }

        gridbar();          // includes release fence for the stores above

        if (t + 1 < Tt) {
#pragma unroll
            for (int nt = 0; nt < 2; ++nt)
#pragma unroll
                for (int e = 0; e < 4; ++e) {
                    pxr[nt][e] = nxr[nt][e];
                    pxz[nt][e] = nxz[nt][e];
                    pxn[nt][e] = nxn[nt][e];
                }
        }
    }
}

// ---------------- kernel 3: out[b] = h_T[b,:] @ W_lin + b_lin -------------------
__global__ void out_kernel(const float* __restrict__ Wlin,
                           const float* __restrict__ blin,
                           float* __restrict__ out)
{
    int w = (blockIdx.x * blockDim.x + threadIdx.x) >> 5;
    int lane = threadIdx.x & 31;
    if (w >= Bx) return;
    const float* h = g_h[0] + (size_t)w * Hh;   // T=256 even -> final in buf 0
    float s = 0.0f;
#pragma unroll
    for (int i = 0; i < Hh / 32; ++i) s += h[lane + 32 * i] * Wlin[lane + 32 * i];
#pragma unroll
    for (int o = 16; o; o >>= 1) s += __shfl_xor_sync(0xffffffffu, s, o);
    if (lane == 0) out[w] = s + blin[0];
}

// ---------------- launch ---------------------------------------------------------
extern "C" void kernel_launch(void* const* d_in, const int* in_sizes, int n_in,
                              void* d_out, int out_size)
{
    const float* x    = (const float*)d_in[0];
    const float* Wih  = (const float*)d_in[1];
    const float* Whh  = (const float*)d_in[2];
    const float* bih  = (const float*)d_in[3];
    const float* bhh  = (const float*)d_in[4];
    const float* Wlin = (const float*)d_in[5];
    const float* blin = (const float*)d_in[6];
    float* out = (float*)d_out;

    cudaFuncSetAttribute(gru_persist_kernel,
                         cudaFuncAttributeMaxDynamicSharedMemorySize, SMEM_BYTES);

    init_kernel<<<(Bx * Hh + 255) / 256, 256>>>();
    wconv_kernel<<<(G3 * Hh + 255) / 256, 256>>>(Whh);
    dim3 gx((Bx * Tt) / 64, G3 / 64);
    xg_kernel<<<gx, 256>>>(x, Wih, bih, bhh);
    gru_persist_kernel<<<NBLK, 256, SMEM_BYTES>>>(bhh);
    out_kernel<<<(Bx * 32) / 256, 256>>>(Wlin, blin, out);
}

// round 12
// speedup vs baseline: 1.1724x; 1.1005x over previous
#include <cuda_runtime.h>
#include <cuda_fp16.h>
#include <math.h>
#include <stdint.h>

#define Bx 512
#define Tt 256
#define Ii 128
#define Hh 512
#define G3 1536

// ---------------- scratch (device globals; no allocation allowed) ----------------
__device__ float g_xg[(size_t)Tt * (size_t)Bx * (size_t)G3]; // [T][B][3H] fp32
__device__ float g_h[2][Bx * Hh];                            // fp32 hidden, ping-pong
__device__ __half g_hhi[2][Bx * Hh];                         // h fp16 hi (perm-k)
__device__ __half g_Whi[(size_t)G3 * Hh];                    // W_hh fp16 hi (perm-k)
__device__ __half g_Wlo[(size_t)G3 * Hh];                    // W_hh fp16 lo (perm-k)

// permutation within each 16-k block so mma fragment (k, k+1, k+8, k+9) is one LDS.64
__device__ __forceinline__ int kperm(int k) {
    return ((k & 7) >> 1) * 4 + (k & 1) + (((k >> 3) & 1) << 1);
}

// ---------------- init: zero h0 (fp32 + fp16 hi), every launch -------------------
__global__ void init_kernel() {
    int i = blockIdx.x * 256 + threadIdx.x;
    if (i < Bx * Hh) {
        g_h[0][i] = 0.0f;
        g_hhi[0][i] = __float2half(0.0f);
    }
}

// ---------------- W_hh -> split fp16 (hi + lo), permuted-k layout ----------------
__global__ void wconv_kernel(const float* __restrict__ Whh) {
    int idx = blockIdx.x * 256 + threadIdx.x;
    if (idx >= G3 * Hh) return;
    int row = idx >> 9, k = idx & 511;
    float w = Whh[idx];
    __half hi = __float2half(w);
    float lo = w - __half2float(hi);
    int kk = (k & ~15) + kperm(k & 15);
    g_Whi[(size_t)row * Hh + kk] = hi;
    g_Wlo[(size_t)row * Hh + kk] = __float2half(lo);
}

// ---------------- kernel 1: xg[t][b][g] = x[b,t,:] @ W_ih[g,:] + bias ------------
// bias = b_ih + b_hh for r/z gates; b_ih only for n gate (b_hh_n sits inside r*hn).
__global__ __launch_bounds__(256) void xg_kernel(
    const float* __restrict__ x, const float* __restrict__ Wih,
    const float* __restrict__ bih, const float* __restrict__ bhh)
{
    __shared__ float As[64][68];
    __shared__ float Bs[64][68];
    const int bt0 = blockIdx.x * 64;
    const int n0  = blockIdx.y * 64;
    const int tid = threadIdx.x;
    const int tx = tid & 15, ty = tid >> 4;

    float acc[4][4];
#pragma unroll
    for (int i = 0; i < 4; ++i)
#pragma unroll
        for (int j = 0; j < 4; ++j) acc[i][j] = 0.0f;

    for (int kc = 0; kc < 2; ++kc) {
        const int kb = kc * 64;
#pragma unroll
        for (int i = 0; i < 4; ++i) {
            int q = tid + 256 * i;
            int r = q >> 4, c4 = q & 15;
            float4 v = *(const float4*)(x + (size_t)(bt0 + r) * Ii + kb + c4 * 4);
            As[c4 * 4 + 0][r] = v.x; As[c4 * 4 + 1][r] = v.y;
            As[c4 * 4 + 2][r] = v.z; As[c4 * 4 + 3][r] = v.w;
        }
#pragma unroll
        for (int i = 0; i < 4; ++i) {
            int q = tid + 256 * i;
            int r = q >> 4, c4 = q & 15;
            float4 v = *(const float4*)(Wih + (size_t)(n0 + r) * Ii + kb + c4 * 4);
            Bs[c4 * 4 + 0][r] = v.x; Bs[c4 * 4 + 1][r] = v.y;
            Bs[c4 * 4 + 2][r] = v.z; Bs[c4 * 4 + 3][r] = v.w;
        }
        __syncthreads();
#pragma unroll 16
        for (int k = 0; k < 64; ++k) {
            float4 a4 = *(const float4*)&As[k][ty * 4];
            float4 b4 = *(const float4*)&Bs[k][tx * 4];
            float av[4] = {a4.x, a4.y, a4.z, a4.w};
            float bv[4] = {b4.x, b4.y, b4.z, b4.w};
#pragma unroll
            for (int i = 0; i < 4; ++i)
#pragma unroll
                for (int j = 0; j < 4; ++j) acc[i][j] += av[i] * bv[j];
        }
        __syncthreads();
    }

#pragma unroll
    for (int i = 0; i < 4; ++i) {
        int bt = bt0 + ty * 4 + i;
        int b = bt / Tt, t = bt % Tt;       // x rows are [B][T]
        float* dst = g_xg + ((size_t)t * Bx + b) * G3 + n0 + tx * 4;
#pragma unroll
        for (int j = 0; j < 4; ++j) {
            int g = n0 + tx * 4 + j;
            float bias = bih[g] + (g < 2 * Hh ? bhh[g] : 0.0f);
            dst[j] = acc[i][j] + bias;
        }
    }
}

// ---------------- fp16 mma.sync helper -------------------------------------------
__device__ __forceinline__ void mma_f16(float* c,
    uint32_t a0, uint32_t a1, uint32_t a2, uint32_t a3,
    uint32_t b0, uint32_t b1)
{
    asm volatile(
        "mma.sync.aligned.m16n8k16.row.col.f32.f16.f16.f32 "
        "{%0,%1,%2,%3},{%4,%5,%6,%7},{%8,%9},{%0,%1,%2,%3};"
        : "+f"(c[0]), "+f"(c[1]), "+f"(c[2]), "+f"(c[3])
        : "r"(a0), "r"(a1), "r"(a2), "r"(a3), "r"(b0), "r"(b1));
}

// smem row strides (fp16 units): 80 -> 160B rows, conflict-free LDS.64 fragments
#define AST 80
#define BST 80
// per-stage partition (fp16 units): A hi only; B hi + lo
#define OFF_AHI 0
#define OFF_BHI (64 * AST)
#define OFF_BLO (64 * AST + 96 * BST)
#define STAGE_ELEMS (64 * AST + 2 * 96 * BST)   // 20480 halves = 40960 B
#define SMEM_BYTES (2 * STAGE_ELEMS * 2)        // 2 stages = 81920 B

// ---------------- kernel 2: one GRU timestep (tensor-core, split-fp16, 2-term) ---
// Double-buffered LDG->reg->STS pipeline, ONE sync per chunk:
//   iter ch: STS(chunk ch+1 from regs) | LDG(chunk ch+2 into regs) | MMA(chunk ch)
// MMAs issued TERM-MAJOR (all 6 accumulators for ah*bh, then all 6 for ah*bl) so
// same-accumulator MMAs are 6 issues apart -> no dependency stalls.
__global__ __launch_bounds__(256) void gru_step_kernel(
    int t, const float* __restrict__ bhh)
{
    extern __shared__ __half sm[];

    const int tid  = threadIdx.x;
    const int lane = tid & 31;
    const int w    = tid >> 5;          // 8 warps
    const int mt   = w >> 1;            // 4 m-tiles of 16 batch rows
    const int jp   = w & 1;             // 2 j-halves of 16 cols
    const int qrow = lane >> 2;         // 0..7
    const int qcol = lane & 3;          // 0..3

    const int btile = blockIdx.x >> 4, jtile = blockIdx.x & 15;
    const int b0 = btile * 64, j0 = jtile * 32;

    const __half* hhi_in = g_hhi[t & 1];

    // staging decomposition (same for every chunk)
    const int sr  = tid >> 3;           // 0..31 (row group; +32/+64 offsets)
    const int pos = tid & 7;            // 16B slot within 128B row

    uint4 ra[2], rb_hi[3], rb_lo[3];    // in-flight chunk registers

    auto load_regs = [&](int ch) {
        const int kb = ch * 64;
#pragma unroll
        for (int i = 0; i < 2; ++i) {
            int r = sr + 32 * i;
            ra[i] = *(const uint4*)(hhi_in + (size_t)(b0 + r) * Hh + kb + pos * 8);
        }
#pragma unroll
        for (int i = 0; i < 3; ++i) {
            int p = sr + 32 * i;
            int grow = ((p >> 5) << 9) + j0 + (p & 31);
            size_t goff = (size_t)grow * Hh + kb + pos * 8;
            rb_hi[i] = *(const uint4*)(g_Whi + goff);
            rb_lo[i] = *(const uint4*)(g_Wlo + goff);
        }
    };
    auto sts_regs = [&](int s) {
        __half* st = sm + s * STAGE_ELEMS;
#pragma unroll
        for (int i = 0; i < 2; ++i) {
            int r = sr + 32 * i;
            *(uint4*)&st[OFF_AHI + r * AST + pos * 8] = ra[i];
        }
#pragma unroll
        for (int i = 0; i < 3; ++i) {
            int p = sr + 32 * i;
            *(uint4*)&st[OFF_BHI + p * BST + pos * 8] = rb_hi[i];
            *(uint4*)&st[OFF_BLO + p * BST + pos * 8] = rb_lo[i];
        }
    };

    // prologue: chunk0 -> stage0; chunk1 in registers
    load_regs(0);
    sts_regs(0);
    load_regs(1);

    // -------- epilogue operand prefetch (overlaps the whole GEMM) --------
    const float* xg_t = g_xg + (size_t)t * Bx * G3;
    const float* hf_in = g_h[t & 1];
    float pre_xr[2][4], pre_xz[2][4], pre_xn[2][4], pre_h[2][4], pre_bn[2][4];
#pragma unroll
    for (int nt = 0; nt < 2; ++nt)
#pragma unroll
        for (int e = 0; e < 4; ++e) {
            int row = b0 + mt * 16 + qrow + ((e >> 1) ? 8 : 0);
            int j   = j0 + jp * 16 + nt * 8 + qcol * 2 + (e & 1);
            const float* xp = xg_t + (size_t)row * G3 + j;
            pre_xr[nt][e] = xp[0];
            pre_xz[nt][e] = xp[Hh];
            pre_xn[nt][e] = xp[2 * Hh];
            pre_h[nt][e]  = hf_in[row * Hh + j];
            pre_bn[nt][e] = bhh[2 * Hh + j];
        }
    __syncthreads();   // stage0 published

    float acc[3][2][4];                 // [gate][n-tile][c-regs]
#pragma unroll
    for (int g = 0; g < 3; ++g)
#pragma unroll
        for (int nt = 0; nt < 2; ++nt)
#pragma unroll
            for (int e = 0; e < 4; ++e) acc[g][nt][e] = 0.0f;

    const int ar0 = mt * 16 + qrow;
    const int ar8 = ar0 + 8;

#pragma unroll 1
    for (int ch = 0; ch < 8; ++ch) {
        // STS chunk ch+1 (regs) into the buffer consumed at ch-1; safe: one
        // barrier separates its last read (mma ch-1) from this write.
        if (ch < 7) sts_regs((ch + 1) & 1);
        if (ch < 6) load_regs(ch + 2);      // LDG issue; consumed next iter

        const __half* st = sm + (ch & 1) * STAGE_ELEMS;
        const __half* As_hi = st + OFF_AHI;
        const __half* Bs_hi = st + OFF_BHI;
        const __half* Bs_lo = st + OFF_BLO;

#pragma unroll
        for (int kt = 0; kt < 4; ++kt) {
            const int aoff = kt * 16 + qcol * 4;
            uint2 a0 = *(const uint2*)&As_hi[ar0 * AST + aoff];
            uint2 a8 = *(const uint2*)&As_hi[ar8 * AST + aoff];
            uint2 bh[3][2], bl[3][2];
#pragma unroll
            for (int g = 0; g < 3; ++g)
#pragma unroll
                for (int nt = 0; nt < 2; ++nt) {
                    int brow = g * 32 + jp * 16 + nt * 8 + qrow;
                    bh[g][nt] = *(const uint2*)&Bs_hi[brow * BST + aoff];
                    bl[g][nt] = *(const uint2*)&Bs_lo[brow * BST + aoff];
                }
            // term-major: 6 independent accumulators between same-acc MMAs
#pragma unroll
            for (int g = 0; g < 3; ++g)
#pragma unroll
                for (int nt = 0; nt < 2; ++nt)
                    mma_f16(acc[g][nt], a0.x, a8.x, a0.y, a8.y,
                            bh[g][nt].x, bh[g][nt].y);
#pragma unroll
            for (int g = 0; g < 3; ++g)
#pragma unroll
                for (int nt = 0; nt < 2; ++nt)
                    mma_f16(acc[g][nt], a0.x, a8.x, a0.y, a8.y,
                            bl[g][nt].x, bl[g][nt].y);
        }
        if (ch < 7) __syncthreads();    // publish stage (ch+1)&1, fence reads
    }

    // -------- epilogue: gates fused in registers --------
    float* hf_out = g_h[(t + 1) & 1];
    __half* hhi_out = g_hhi[(t + 1) & 1];

#pragma unroll
    for (int nt = 0; nt < 2; ++nt)
#pragma unroll
        for (int e = 0; e < 4; ++e) {
            int row = b0 + mt * 16 + qrow + ((e >> 1) ? 8 : 0);
            int j   = j0 + jp * 16 + nt * 8 + qcol * 2 + (e & 1);
            float hr = acc[0][nt][e];
            float hz = acc[1][nt][e];
            float hn = acc[2][nt][e] + pre_bn[nt][e];   // b_hh_n inside r*hn
            float r = 1.0f / (1.0f + expf(-(pre_xr[nt][e] + hr)));
            float z = 1.0f / (1.0f + expf(-(pre_xz[nt][e] + hz)));
            float n = tanhf(pre_xn[nt][e] + r * hn);
            float hnew = (1.0f - z) * n + z * pre_h[nt][e];
            hf_out[row * Hh + j] = hnew;
            int jj = (j & ~15) + kperm(j & 15);
            hhi_out[row * Hh + jj] = __float2half(hnew);
        }
}

// ---------------- kernel 3: out[b] = h_T[b,:] @ W_lin + b_lin -------------------
__global__ void out_kernel(const float* __restrict__ Wlin,
                           const float* __restrict__ blin,
                           float* __restrict__ out)
{
    int w = (blockIdx.x * blockDim.x + threadIdx.x) >> 5;
    int lane = threadIdx.x & 31;
    if (w >= Bx) return;
    const float* h = g_h[0] + (size_t)w * Hh;   // T=256 even -> final in buf 0
    float s = 0.0f;
#pragma unroll
    for (int i = 0; i < Hh / 32; ++i) s += h[lane + 32 * i] * Wlin[lane + 32 * i];
#pragma unroll
    for (int o = 16; o; o >>= 1) s += __shfl_xor_sync(0xffffffffu, s, o);
    if (lane == 0) out[w] = s + blin[0];
}

// ---------------- launch ---------------------------------------------------------
extern "C" void kernel_launch(void* const* d_in, const int* in_sizes, int n_in,
                              void* d_out, int out_size)
{
    const float* x    = (const float*)d_in[0];
    const float* Wih  = (const float*)d_in[1];
    const float* Whh  = (const float*)d_in[2];
    const float* bih  = (const float*)d_in[3];
    const float* bhh  = (const float*)d_in[4];
    const float* Wlin = (const float*)d_in[5];
    const float* blin = (const float*)d_in[6];
    float* out = (float*)d_out;

    cudaFuncSetAttribute(gru_step_kernel,
                         cudaFuncAttributeMaxDynamicSharedMemorySize, SMEM_BYTES);

    init_kernel<<<(Bx * Hh + 255) / 256, 256>>>();
    wconv_kernel<<<(G3 * Hh + 255) / 256, 256>>>(Whh);
    dim3 gx((Bx * Tt) / 64, G3 / 64);
    xg_kernel<<<gx, 256>>>(x, Wih, bih, bhh);
    for (int t = 0; t < Tt; ++t)
        gru_step_kernel<<<128, 256, SMEM_BYTES>>>(t, bhh);
    out_kernel<<<(Bx * 32) / 256, 256>>>(Wlin, blin, out);
}

// round 13
// speedup vs baseline: 1.5848x; 1.3518x over previous
#include <cuda_runtime.h>
#include <cuda_fp16.h>
#include <math.h>
#include <stdint.h>

#define Bx 512
#define Tt 256
#define Ii 128
#define Hh 512
#define G3 1536
#define BT (Bx * Tt)

// ---------------- scratch (device globals; no allocation allowed) ----------------
__device__ float g_xg[(size_t)Tt * (size_t)Bx * (size_t)G3]; // [T][B][3H] fp32
__device__ float g_h[2][Bx * Hh];                            // fp32 hidden, ping-pong
__device__ __half g_hhi[2][Bx * Hh];                         // h fp16 hi (perm-k)
__device__ __half g_Whi[(size_t)G3 * Hh];                    // W_hh fp16 hi (perm-k)
__device__ __half g_Wlo[(size_t)G3 * Hh];                    // W_hh fp16 lo (perm-k)
__device__ __half g_xhi[(size_t)BT * Ii];                    // x fp16 hi (perm-k)
__device__ __half g_Wihhi[(size_t)G3 * Ii];                  // W_ih fp16 hi (perm-k)
__device__ __half g_Wihlo[(size_t)G3 * Ii];                  // W_ih fp16 lo (perm-k)

// permutation within each 16-k block so mma fragment (k, k+1, k+8, k+9) is one LDS.64
__device__ __forceinline__ int kperm(int k) {
    return ((k & 7) >> 1) * 4 + (k & 1) + (((k >> 3) & 1) << 1);
}

// ---------------- init: zero h0 (fp32 + fp16 hi), every launch -------------------
__global__ void init_kernel() {
    int i = blockIdx.x * 256 + threadIdx.x;
    if (i < Bx * Hh) {
        g_h[0][i] = 0.0f;
        g_hhi[0][i] = __float2half(0.0f);
    }
}

// ---------------- W_hh -> split fp16 (hi + lo), permuted-k layout ----------------
__global__ void wconv_kernel(const float* __restrict__ Whh) {
    int idx = blockIdx.x * 256 + threadIdx.x;
    if (idx >= G3 * Hh) return;
    int row = idx >> 9, k = idx & 511;
    float w = Whh[idx];
    __half hi = __float2half(w);
    float lo = w - __half2float(hi);
    int kk = (k & ~15) + kperm(k & 15);
    g_Whi[(size_t)row * Hh + kk] = hi;
    g_Wlo[(size_t)row * Hh + kk] = __float2half(lo);
}

// ---------------- x -> fp16 hi (perm-k); W_ih -> fp16 hi+lo (perm-k) -------------
__global__ void xconv_kernel(const float* __restrict__ x) {
    size_t idx = (size_t)blockIdx.x * 256 + threadIdx.x;
    if (idx >= (size_t)BT * Ii) return;
    int k = (int)(idx & (Ii - 1));
    size_t row = idx >> 7;
    int kk = (k & ~15) + kperm(k & 15);
    g_xhi[row * Ii + kk] = __float2half(x[idx]);
}
__global__ void wihconv_kernel(const float* __restrict__ Wih) {
    int idx = blockIdx.x * 256 + threadIdx.x;
    if (idx >= G3 * Ii) return;
    int row = idx >> 7, k = idx & (Ii - 1);
    float w = Wih[idx];
    __half hi = __float2half(w);
    float lo = w - __half2float(hi);
    int kk = (k & ~15) + kperm(k & 15);
    g_Wihhi[(size_t)row * Ii + kk] = hi;
    g_Wihlo[(size_t)row * Ii + kk] = __float2half(lo);
}

// ---------------- fp16 mma.sync helper -------------------------------------------
__device__ __forceinline__ void mma_f16(float* c,
    uint32_t a0, uint32_t a1, uint32_t a2, uint32_t a3,
    uint32_t b0, uint32_t b1)
{
    asm volatile(
        "mma.sync.aligned.m16n8k16.row.col.f32.f16.f16.f32 "
        "{%0,%1,%2,%3},{%4,%5,%6,%7},{%8,%9},{%0,%1,%2,%3};"
        : "+f"(c[0]), "+f"(c[1]), "+f"(c[2]), "+f"(c[3])
        : "r"(a0), "r"(a1), "r"(a2), "r"(a3), "r"(b0), "r"(b1));
}

// ---------------- kernel 1: xg via fp16 MMA (2-term split) -----------------------
// Block: 64 bt-rows x 64 gate-cols, K=128 as 2 chunks of 64 (single buffer).
// Warp w: mt=w>>1 (16 rows), jp=w&1 (32 cols = 4 n8 tiles).
#define XAST 80
__global__ __launch_bounds__(256) void xg_mma_kernel(
    const float* __restrict__ bih, const float* __restrict__ bhh)
{
    __shared__ __half As[64 * XAST];
    __shared__ __half Bh[64 * XAST];
    __shared__ __half Bl[64 * XAST];

    const int tid  = threadIdx.x;
    const int lane = tid & 31;
    const int w    = tid >> 5;
    const int mt   = w >> 1, jp = w & 1;
    const int qrow = lane >> 2, qcol = lane & 3;

    const int bt0 = blockIdx.x * 64;
    const int n0  = blockIdx.y * 64;

    const int sr  = tid >> 3;     // 0..31
    const int pos = tid & 7;

    float acc[4][4];
#pragma unroll
    for (int nt = 0; nt < 4; ++nt)
#pragma unroll
        for (int e = 0; e < 4; ++e) acc[nt][e] = 0.0f;

    const int ar0 = mt * 16 + qrow, ar8 = ar0 + 8;

#pragma unroll
    for (int ch = 0; ch < 2; ++ch) {
        const int kb = ch * 64;
        __syncthreads();            // prior chunk consumed
#pragma unroll
        for (int i = 0; i < 2; ++i) {
            int r = sr + 32 * i;
            *(uint4*)&As[r * XAST + pos * 8] =
                *(const uint4*)(g_xhi + (size_t)(bt0 + r) * Ii + kb + pos * 8);
            size_t goff = (size_t)(n0 + r) * Ii + kb + pos * 8;
            *(uint4*)&Bh[r * XAST + pos * 8] = *(const uint4*)(g_Wihhi + goff);
            *(uint4*)&Bl[r * XAST + pos * 8] = *(const uint4*)(g_Wihlo + goff);
        }
        __syncthreads();
#pragma unroll
        for (int kt = 0; kt < 4; ++kt) {
            const int aoff = kt * 16 + qcol * 4;
            uint2 a0 = *(const uint2*)&As[ar0 * XAST + aoff];
            uint2 a8 = *(const uint2*)&As[ar8 * XAST + aoff];
            uint2 bh[4], bl[4];
#pragma unroll
            for (int nt = 0; nt < 4; ++nt) {
                int brow = jp * 32 + nt * 8 + qrow;
                bh[nt] = *(const uint2*)&Bh[brow * XAST + aoff];
                bl[nt] = *(const uint2*)&Bl[brow * XAST + aoff];
            }
#pragma unroll
            for (int nt = 0; nt < 4; ++nt)
                mma_f16(acc[nt], a0.x, a8.x, a0.y, a8.y, bh[nt].x, bh[nt].y);
#pragma unroll
            for (int nt = 0; nt < 4; ++nt)
                mma_f16(acc[nt], a0.x, a8.x, a0.y, a8.y, bl[nt].x, bl[nt].y);
        }
    }

    // epilogue: scatter to g_xg[t*B + b][col] with bias folded
#pragma unroll
    for (int nt = 0; nt < 4; ++nt)
#pragma unroll
        for (int e = 0; e < 4; ++e) {
            int bt = bt0 + mt * 16 + qrow + ((e >> 1) ? 8 : 0);
            int col = n0 + jp * 32 + nt * 8 + qcol * 2 + (e & 1);
            int b = bt / Tt, t = bt % Tt;      // x rows are [B][T]
            float bias = bih[col] + (col < 2 * Hh ? bhh[col] : 0.0f);
            g_xg[((size_t)t * Bx + b) * G3 + col] = acc[nt][e] + bias;
        }
}

// smem row stride (fp16 units): 80 -> 160B rows, conflict-free LDS.64 fragments
#define AST 80
#define BST 80
// per-stage partition (fp16 units): A hi (64 rows); B hi + lo (48 rows each)
#define OFF_AHI 0
#define OFF_BHI (64 * AST)
#define OFF_BLO (64 * AST + 48 * BST)
#define STAGE_ELEMS (64 * AST + 2 * 48 * BST)   // 12800 halves = 25600 B
#define SMEM_BYTES (2 * STAGE_ELEMS * 2)        // 2 stages = 51200 B

// ---------------- kernel 2: one GRU timestep (fp16 MMA, 2-term, 2 CTAs/SM) -------
// 256 blocks = 8 b-tiles(64) x 32 j-tiles(16) -> 2 CTAs co-resident per SM with
// INDEPENDENT barriers (fills the latency round 12 exposed). Same double-buffered
// LDG->reg->STS pipeline, one sync per chunk, term-major MMA issue.
__global__ __launch_bounds__(256, 2) void gru_step_kernel(
    int t, const float* __restrict__ bhh)
{
    extern __shared__ __half sm[];

    const int tid  = threadIdx.x;
    const int lane = tid & 31;
    const int w    = tid >> 5;          // 8 warps
    const int mt   = w >> 1;            // 4 m-tiles of 16 batch rows
    const int jp   = w & 1;             // 2 n8 halves of the 16 cols
    const int qrow = lane >> 2;
    const int qcol = lane & 3;

    const int btile = blockIdx.x >> 5, jtile = blockIdx.x & 31;
    const int b0 = btile * 64, j0 = jtile * 16;

    const __half* hhi_in = g_hhi[t & 1];

    const int sr  = tid >> 3;           // 0..31
    const int pos = tid & 7;

    uint4 ra[2], rb_hi[2], rb_lo[2];

    auto load_regs = [&](int ch) {
        const int kb = ch * 64;
#pragma unroll
        for (int i = 0; i < 2; ++i) {
            int r = sr + 32 * i;
            ra[i] = *(const uint4*)(hhi_in + (size_t)(b0 + r) * Hh + kb + pos * 8);
        }
        {
            int p = sr;                                  // rows 0..31
            int grow = (p >> 4) * Hh + j0 + (p & 15);
            size_t goff = (size_t)grow * Hh + kb + pos * 8;
            rb_hi[0] = *(const uint4*)(g_Whi + goff);
            rb_lo[0] = *(const uint4*)(g_Wlo + goff);
        }
        if (sr < 16) {                                   // rows 32..47 (n gate)
            int p = sr + 32;
            int grow = 2 * Hh + j0 + (p & 15);
            size_t goff = (size_t)grow * Hh + kb + pos * 8;
            rb_hi[1] = *(const uint4*)(g_Whi + goff);
            rb_lo[1] = *(const uint4*)(g_Wlo + goff);
        }
    };
    auto sts_regs = [&](int s) {
        __half* st = sm + s * STAGE_ELEMS;
#pragma unroll
        for (int i = 0; i < 2; ++i) {
            int r = sr + 32 * i;
            *(uint4*)&st[OFF_AHI + r * AST + pos * 8] = ra[i];
        }
        *(uint4*)&st[OFF_BHI + sr * BST + pos * 8] = rb_hi[0];
        *(uint4*)&st[OFF_BLO + sr * BST + pos * 8] = rb_lo[0];
        if (sr < 16) {
            int p = sr + 32;
            *(uint4*)&st[OFF_BHI + p * BST + pos * 8] = rb_hi[1];
            *(uint4*)&st[OFF_BLO + p * BST + pos * 8] = rb_lo[1];
        }
    };

    load_regs(0);
    sts_regs(0);
    load_regs(1);

    // -------- epilogue operand prefetch (overlaps the whole GEMM) --------
    const float* xg_t = g_xg + (size_t)t * Bx * G3;
    const float* hf_in = g_h[t & 1];
    float pre_xr[4], pre_xz[4], pre_xn[4], pre_h[4], pre_bn[4];
#pragma unroll
    for (int e = 0; e < 4; ++e) {
        int row = b0 + mt * 16 + qrow + ((e >> 1) ? 8 : 0);
        int j   = j0 + jp * 8 + qcol * 2 + (e & 1);
        const float* xp = xg_t + (size_t)row * G3 + j;
        pre_xr[e] = xp[0];
        pre_xz[e] = xp[Hh];
        pre_xn[e] = xp[2 * Hh];
        pre_h[e]  = hf_in[row * Hh + j];
        pre_bn[e] = bhh[2 * Hh + j];
    }
    __syncthreads();   // stage0 published

    float acc[3][4];
#pragma unroll
    for (int g = 0; g < 3; ++g)
#pragma unroll
        for (int e = 0; e < 4; ++e) acc[g][e] = 0.0f;

    const int ar0 = mt * 16 + qrow, ar8 = ar0 + 8;

#pragma unroll 1
    for (int ch = 0; ch < 8; ++ch) {
        if (ch < 7) sts_regs((ch + 1) & 1);
        if (ch < 6) load_regs(ch + 2);

        const __half* st = sm + (ch & 1) * STAGE_ELEMS;
        const __half* As_hi = st + OFF_AHI;
        const __half* Bs_hi = st + OFF_BHI;
        const __half* Bs_lo = st + OFF_BLO;

#pragma unroll
        for (int kt = 0; kt < 4; ++kt) {
            const int aoff = kt * 16 + qcol * 4;
            uint2 a0 = *(const uint2*)&As_hi[ar0 * AST + aoff];
            uint2 a8 = *(const uint2*)&As_hi[ar8 * AST + aoff];
            uint2 bh[3], bl[3];
#pragma unroll
            for (int g = 0; g < 3; ++g) {
                int brow = g * 16 + jp * 8 + qrow;
                bh[g] = *(const uint2*)&Bs_hi[brow * BST + aoff];
                bl[g] = *(const uint2*)&Bs_lo[brow * BST + aoff];
            }
#pragma unroll
            for (int g = 0; g < 3; ++g)
                mma_f16(acc[g], a0.x, a8.x, a0.y, a8.y, bh[g].x, bh[g].y);
#pragma unroll
            for (int g = 0; g < 3; ++g)
                mma_f16(acc[g], a0.x, a8.x, a0.y, a8.y, bl[g].x, bl[g].y);
        }
        if (ch < 7) __syncthreads();
    }

    // -------- epilogue: gates fused in registers --------
    float* hf_out = g_h[(t + 1) & 1];
    __half* hhi_out = g_hhi[(t + 1) & 1];

#pragma unroll
    for (int e = 0; e < 4; ++e) {
        int row = b0 + mt * 16 + qrow + ((e >> 1) ? 8 : 0);
        int j   = j0 + jp * 8 + qcol * 2 + (e & 1);
        float hr = acc[0][e];
        float hz = acc[1][e];
        float hn = acc[2][e] + pre_bn[e];   // b_hh_n inside r*hn
        float r = 1.0f / (1.0f + expf(-(pre_xr[e] + hr)));
        float z = 1.0f / (1.0f + expf(-(pre_xz[e] + hz)));
        float n = tanhf(pre_xn[e] + r * hn);
        float hnew = (1.0f - z) * n + z * pre_h[e];
        hf_out[row * Hh + j] = hnew;
        int jj = (j & ~15) + kperm(j & 15);
        hhi_out[row * Hh + jj] = __float2half(hnew);
    }
}

// ---------------- kernel 3: out[b] = h_T[b,:] @ W_lin + b_lin -------------------
__global__ void out_kernel(const float* __restrict__ Wlin,
                           const float* __restrict__ blin,
                           float* __restrict__ out)
{
    int w = (blockIdx.x * blockDim.x + threadIdx.x) >> 5;
    int lane = threadIdx.x & 31;
    if (w >= Bx) return;
    const float* h = g_h[0] + (size_t)w * Hh;   // T=256 even -> final in buf 0
    float s = 0.0f;
#pragma unroll
    for (int i = 0; i < Hh / 32; ++i) s += h[lane + 32 * i] * Wlin[lane + 32 * i];
#pragma unroll
    for (int o = 16; o; o >>= 1) s += __shfl_xor_sync(0xffffffffu, s, o);
    if (lane == 0) out[w] = s + blin[0];
}

// ---------------- launch ---------------------------------------------------------
extern "C" void kernel_launch(void* const* d_in, const int* in_sizes, int n_in,
                              void* d_out, int out_size)
{
    const float* x    = (const float*)d_in[0];
    const float* Wih  = (const float*)d_in[1];
    const float* Whh  = (const float*)d_in[2];
    const float* bih  = (const float*)d_in[3];
    const float* bhh  = (const float*)d_in[4];
    const float* Wlin = (const float*)d_in[5];
    const float* blin = (const float*)d_in[6];
    float* out = (float*)d_out;

    cudaFuncSetAttribute(gru_step_kernel,
                         cudaFuncAttributeMaxDynamicSharedMemorySize, SMEM_BYTES);

    init_kernel<<<(Bx * Hh + 255) / 256, 256>>>();
    wconv_kernel<<<(G3 * Hh + 255) / 256, 256>>>(Whh);
    xconv_kernel<<<(int)(((size_t)BT * Ii + 255) / 256), 256>>>(x);
    wihconv_kernel<<<(G3 * Ii + 255) / 256, 256>>>(Wih);
    dim3 gx(BT / 64, G3 / 64);
    xg_mma_kernel<<<gx, 256>>>(bih, bhh);
    for (int t = 0; t < Tt; ++t)
        gru_step_kernel<<<256, 256, SMEM_BYTES>>>(t, bhh);
    out_kernel<<<(Bx * 32) / 256, 256>>>(Wlin, blin, out);
}